// round 15
// baseline (speedup 1.0000x reference)
#include <cuda_runtime.h>
#include <cuda_fp16.h>
#include <cstdint>

static constexpr int DIM = 6144;
static constexpr int NQ  = 512;
static constexpr int MT  = 128;         // CTA M tile
static constexpr int NT  = 256;         // CTA N tile
static constexpr int KC  = 32;          // K elements per chunk
static constexpr int NCH = DIM / KC;    // 192
static constexpr int RS  = 80;          // fp16 row pitch (conflict-free)
static constexpr int NTHREADS = 512;
static constexpr int BSTAGES = 4;       // cpB(it+2) vs mma(it-1): needs 4

// ---------------- device scratch ----------------
__device__ __align__(16) __half g_qh[(size_t)NQ * DIM];   // normalized queries fp16
__device__ float g_cut[NQ];
__device__ int      g_part[NQ];
__device__ unsigned g_done[NQ / NT];

// ---------------- PTX helpers ----------------
__device__ __forceinline__ uint32_t smem_u32(const void* p) {
    uint32_t a;
    asm("{ .reg .u64 t; cvta.to.shared.u64 t, %1; cvt.u32.u64 %0, t; }" : "=r"(a) : "l"(p));
    return a;
}
#define CP_ASYNC16CG(saddr, gptr)                                                \
    asm volatile("cp.async.cg.shared.global [%0], [%1], 16;"                     \
                 :: "r"(saddr), "l"(__cvta_generic_to_global(gptr)) : "memory")
#define CP_COMMIT() asm volatile("cp.async.commit_group;" ::: "memory")
#define CP_WAIT(N)  asm volatile("cp.async.wait_group %0;" :: "n"(N) : "memory")
#define LDSM4(r, addr)                                                           \
    asm volatile("ldmatrix.sync.aligned.m8n8.x4.shared.b16 {%0,%1,%2,%3}, [%4];" \
                 : "=r"((r)[0]), "=r"((r)[1]), "=r"((r)[2]), "=r"((r)[3])        \
                 : "r"(addr))
#define MMA16816(d, a, b0, b1)                                                   \
    asm volatile("mma.sync.aligned.m16n8k16.row.col.f32.f16.f16.f32 "            \
                 "{%0,%1,%2,%3}, {%4,%5,%6,%7}, {%8,%9}, {%0,%1,%2,%3};"         \
                 : "+f"((d)[0]), "+f"((d)[1]), "+f"((d)[2]), "+f"((d)[3])        \
                 : "r"((a)[0]), "r"((a)[1]), "r"((a)[2]), "r"((a)[3]),           \
                   "r"(b0), "r"(b1))
#define STS16(addr, u0, u1, u2, u3)                                              \
    asm volatile("st.shared.v4.b32 [%0], {%1,%2,%3,%4};"                         \
                 :: "r"(addr), "r"(u0), "r"(u1), "r"(u2), "r"(u3) : "memory")

__device__ __forceinline__ uint32_t packh2(float a, float b) {
    __half2 h = __floats2half2_rn(a, b);
    return *reinterpret_cast<uint32_t*>(&h);
}

// =====================================================================
// Prep: cuts + normalized fp16 queries (inputs disambiguated on-device)
// =====================================================================
__global__ __launch_bounds__(256) void prep_kernel(
    const float* __restrict__ cand0, const float* __restrict__ cand1)
{
    __shared__ float sred[3 * 8];
    __shared__ float s_inv;
    bool c0_neg = false;
    #pragma unroll
    for (int i = 0; i < 64; ++i) c0_neg |= (cand0[i] < 0.f);
    const float* queries = c0_neg ? cand0 : cand1;
    const float* truths  = c0_neg ? cand1 : cand0;

    int q = blockIdx.x;
    int tid = threadIdx.x;
    const float* qp = queries + (size_t)q * DIM;
    const float* tp = truths + (size_t)q * DIM;

    float qq = 0.f, tt = 0.f, qt = 0.f;
    for (int i = tid; i < DIM; i += 256) {
        float a = qp[i], b = tp[i];
        qq = fmaf(a, a, qq); tt = fmaf(b, b, tt); qt = fmaf(a, b, qt);
    }
    #pragma unroll
    for (int o = 16; o; o >>= 1) {
        qq += __shfl_down_sync(0xffffffffu, qq, o);
        tt += __shfl_down_sync(0xffffffffu, tt, o);
        qt += __shfl_down_sync(0xffffffffu, qt, o);
    }
    if ((tid & 31) == 0) {
        int w = tid >> 5;
        sred[w] = qq; sred[8 + w] = tt; sred[16 + w] = qt;
    }
    __syncthreads();
    if (tid == 0) {
        float QQ = 0.f, TT = 0.f, QT = 0.f;
        #pragma unroll
        for (int w = 0; w < 8; ++w) { QQ += sred[w]; TT += sred[8 + w]; QT += sred[16 + w]; }
        float nq = fmaxf(sqrtf(QQ), 1e-12f);
        float nt = fmaxf(sqrtf(TT), 1e-12f);
        float th = QT / (nq * nt);
        g_cut[q] = th - (1e-8f + 1e-5f * fabsf(th));
        s_inv = 1.0f / nq;
    }
    __syncthreads();
    float inv = s_inv;
    for (int i = tid; i < DIM; i += 256)
        g_qh[(size_t)q * DIM + i] = __float2half_rn(qp[i] * inv);
}

// =====================================================================
// Main: 128x256 fp16 mma.sync GEMM; A via LDG->reg convert (no fp32
// staging), B via cp.async.cg; single-barrier convert-lead pipeline
// =====================================================================
static constexpr uint32_t A16SZ = MT * RS;   // 10240
static constexpr uint32_t BSZ   = NT * RS;   // 20480

struct __align__(16) GSmem {
    float cut[NT];
    int   cnt[NT];
    float srn2[MT];
    int   last;
    int   pad[3];
    __align__(16) char a16[2][A16SZ];
    __align__(16) char b[BSTAGES][BSZ];
};
static constexpr uint32_t SMEM_SZ = sizeof(GSmem);   // ~103KB

__global__ __launch_bounds__(NTHREADS, 1) void gemm_count_kernel(
    const float* __restrict__ data, int n_rows, float* __restrict__ out)
{
    extern __shared__ __align__(16) char smraw[];
    GSmem& s = *reinterpret_cast<GSmem*>(smraw);
    const uint32_t a16_base = smem_u32(s.a16);
    const uint32_t b_base   = smem_u32(s.b);
    const int tid  = threadIdx.x;
    const int lane = tid & 31;
    const int wid  = tid >> 5;          // 0..15
    const int wm   = wid & 1;           // M half (64 rows)
    const int wn   = wid >> 1;          // N eighth (32 cols)
    const int nb   = blockIdx.x;        // 0..1
    const int qb   = nb * NT;
    const int m_base = blockIdx.y * MT;

    for (int i = tid; i < NT; i += NTHREADS) {
        s.cut[i] = g_cut[qb + i];
        s.cnt[i] = 0;
    }
    if (tid < MT) s.srn2[tid] = 0.f;

    // ---- A: LDG fp32 -> regs. thread t -> row t>>2, 8-float quarter t&3 ----
    const int arow = tid >> 2;
    const int ac   = tid & 3;
    const bool arow_ok = (m_base + arow) < n_rows;
    const float* aptr = data + (size_t)(m_base + arow) * DIM + ac * 8;
    const uint32_t a_sts = (uint32_t)arow * RS + ac * 16;
    float4 bufA[2];
    auto ldgA = [&](int it) {
        if (arow_ok) {
            const float4* p = (const float4*)(aptr + (size_t)it * KC);
            bufA[0] = p[0]; bufA[1] = p[1];
        } else {
            bufA[0] = bufA[1] = make_float4(0.f, 0.f, 0.f, 0.f);
        }
    };

    // ---- B: cp.async.cg fp16, 4 stages ----
    const __half* gB = g_qh + (size_t)qb * DIM;
    auto cpB = [&](int it) {
        const int p = it % BSTAGES;
        const int k0 = it * KC;
        #pragma unroll
        for (int i = 0; i < 2; ++i) {       // 1024 16B segments
            int idx = tid + i * NTHREADS;
            int row = idx >> 2, c = idx & 3;
            CP_ASYNC16CG(b_base + p * BSZ + row * RS + c * 16,
                         gB + (size_t)row * DIM + k0 + c * 8);
        }
    };

    float acc[4][4][4];
    #pragma unroll
    for (int i = 0; i < 4; ++i)
        #pragma unroll
        for (int j = 0; j < 4; ++j)
            #pragma unroll
            for (int k = 0; k < 4; ++k) acc[i][j][k] = 0.f;

    float norm2 = 0.f;

    // ldmatrix base offsets (audited R13 mappings)
    const uint32_t a_off0 = (uint32_t)(wm * 64 + (lane & 15)) * RS + (lane >> 4) * 16;
    const uint32_t b_off0 = (uint32_t)(wn * 32 + ((lane >> 4) << 3) + (lane & 7)) * RS
                          + ((lane >> 3) & 1) * 16;

    ldgA(0);
    cpB(0); CP_COMMIT();
    cpB(1); CP_COMMIT();

    for (int it = 0; it <= NCH; ++it) {
        __syncthreads();    // publishes convert(it-1) a16 + cpB(it) stage;
                            // retires mma(it-2)

        if (it < NCH) {
            // ---- convert chunk `it`: bufA regs -> fp16 a16[it&1]; norm2 ----
            float4 v0 = bufA[0], v1 = bufA[1];
            norm2 = fmaf(v0.x, v0.x, norm2); norm2 = fmaf(v0.y, v0.y, norm2);
            norm2 = fmaf(v0.z, v0.z, norm2); norm2 = fmaf(v0.w, v0.w, norm2);
            norm2 = fmaf(v1.x, v1.x, norm2); norm2 = fmaf(v1.y, v1.y, norm2);
            norm2 = fmaf(v1.z, v1.z, norm2); norm2 = fmaf(v1.w, v1.w, norm2);
            STS16(a16_base + (uint32_t)(it & 1) * A16SZ + a_sts,
                  packh2(v0.x, v0.y), packh2(v0.z, v0.w),
                  packh2(v1.x, v1.y), packh2(v1.z, v1.w));
        }
        if (it + 1 < NCH) ldgA(it + 1);
        if (it + 2 < NCH) cpB(it + 2);
        CP_COMMIT();
        CP_WAIT(1);         // own cpB(it+1) landed (published at next barrier)

        if (it >= 1) {
            // ---- mma chunk `it-1`: a16[(it-1)&1], b[(it-1)%4] ----
            const int mi = it - 1;
            const uint32_t a_fr = a16_base + (uint32_t)(mi & 1) * A16SZ + a_off0;
            const uint32_t b_fr = b_base + (uint32_t)(mi % BSTAGES) * BSZ + b_off0;
            #pragma unroll
            for (int ks = 0; ks < 2; ++ks) {
                uint32_t af[4][4];
                #pragma unroll
                for (int ma = 0; ma < 4; ++ma)
                    LDSM4(af[ma], a_fr + (uint32_t)ma * 16 * RS + ks * 32);
                uint32_t bf[2][4];
                #pragma unroll
                for (int pr = 0; pr < 2; ++pr)
                    LDSM4(bf[pr], b_fr + (uint32_t)pr * 16 * RS + ks * 32);
                #pragma unroll
                for (int np = 0; np < 4; ++np) {
                    uint32_t b0 = bf[np >> 1][(np & 1) * 2];
                    uint32_t b1 = bf[np >> 1][(np & 1) * 2 + 1];
                    #pragma unroll
                    for (int ma = 0; ma < 4; ++ma)
                        MMA16816(acc[ma][np], af[ma], b0, b1);
                }
            }
        }
    }

    // ---- finish row norms (4 threads per row) ----
    atomicAdd(&s.srn2[arow], norm2);
    __syncthreads();

    // ---- count epilogue ----
    float nr0v[4], nr1v[4];
    bool  ok0v[4], ok1v[4];
    #pragma unroll
    for (int ma = 0; ma < 4; ++ma) {
        int l0 = wm * 64 + ma * 16 + (lane >> 2);
        nr0v[ma] = sqrtf(s.srn2[l0]);
        nr1v[ma] = sqrtf(s.srn2[l0 + 8]);
        ok0v[ma] = (m_base + l0) < n_rows;
        ok1v[ma] = (m_base + l0 + 8) < n_rows;
    }
    #pragma unroll
    for (int na = 0; na < 4; ++na) {
        int cn = wn * 32 + na * 8 + 2 * (lane & 3);
        float cut0 = s.cut[cn], cut1 = s.cut[cn + 1];
        int c0 = 0, c1 = 0;
        #pragma unroll
        for (int ma = 0; ma < 4; ++ma) {
            c0 += (ok0v[ma] && acc[ma][na][0] >= nr0v[ma] * cut0);
            c0 += (ok1v[ma] && acc[ma][na][2] >= nr1v[ma] * cut0);
            c1 += (ok0v[ma] && acc[ma][na][1] >= nr0v[ma] * cut1);
            c1 += (ok1v[ma] && acc[ma][na][3] >= nr1v[ma] * cut1);
        }
        int pk = c0 | (c1 << 16);
        pk += __shfl_xor_sync(0xffffffffu, pk, 4);
        pk += __shfl_xor_sync(0xffffffffu, pk, 8);
        pk += __shfl_xor_sync(0xffffffffu, pk, 16);
        if (lane < 4) {
            atomicAdd(&s.cnt[cn], pk & 0xffff);
            atomicAdd(&s.cnt[cn + 1], pk >> 16);
        }
    }
    __syncthreads();

    // ---- cross-CTA last-block reduction (float output) ----
    if (tid < NT) atomicAdd(&g_part[qb + tid], s.cnt[tid]);
    __threadfence();
    __syncthreads();
    if (tid == 0) {
        unsigned t = atomicAdd(&g_done[nb], 1u);
        s.last = (t == gridDim.y - 1);
    }
    __syncthreads();
    if (s.last) {
        __threadfence();
        if (tid < NT) {
            int v = atomicExch(&g_part[qb + tid], 0);
            out[qb + tid] = (float)(v - 1);
        }
        if (tid == 0) atomicExch(&g_done[nb], 0u);
    }
}

// =====================================================================
extern "C" void kernel_launch(void* const* d_in, const int* in_sizes, int n_in,
                              void* d_out, int out_size)
{
    int i_data = 0;
    for (int i = 1; i < n_in && i < 3; ++i)
        if (in_sizes[i] > in_sizes[i_data]) i_data = i;
    int i_c0 = (i_data == 0) ? 1 : 0;
    int i_c1 = 3 - i_data - i_c0;

    const float* data  = (const float*)d_in[i_data];
    const float* cand0 = (const float*)d_in[i_c0];
    const float* cand1 = (const float*)d_in[i_c1];
    float* out = (float*)d_out;
    const int n_rows = in_sizes[i_data] / DIM;       // 50000

    prep_kernel<<<NQ, 256>>>(cand0, cand1);

    cudaFuncSetAttribute(gemm_count_kernel,
                         cudaFuncAttributeMaxDynamicSharedMemorySize, SMEM_SZ);
    dim3 grid(NQ / NT, (n_rows + MT - 1) / MT);      // (2, 391)
    gemm_count_kernel<<<grid, NTHREADS, SMEM_SZ>>>(data, n_rows, out);
}

// round 16
// speedup vs baseline: 1.4542x; 1.4542x over previous
#include <cuda_runtime.h>
#include <cuda_fp16.h>
#include <cstdint>

static constexpr int DIM = 6144;
static constexpr int NQ  = 512;
static constexpr int MT  = 128;         // CTA M tile
static constexpr int NT  = 256;         // CTA N tile
static constexpr int KC  = 32;          // K elements per chunk
static constexpr int NCH = DIM / KC;    // 192
static constexpr int RS  = 80;          // fp16 row pitch (conflict-free)
static constexpr int PS  = 144;         // fp32 staging row pitch (conflict-free)
static constexpr int NTHREADS = 512;
static constexpr int STAGES = 4;        // cp(it+2) vs mma(it-1): needs 4

// ---------------- device scratch ----------------
__device__ __align__(16) __half g_qh[(size_t)NQ * DIM];   // normalized queries fp16
__device__ float g_cut[NQ];
__device__ int      g_part[NQ];
__device__ unsigned g_done[NQ / NT];

// ---------------- PTX helpers ----------------
__device__ __forceinline__ uint32_t smem_u32(const void* p) {
    uint32_t a;
    asm("{ .reg .u64 t; cvta.to.shared.u64 t, %1; cvt.u32.u64 %0, t; }" : "=r"(a) : "l"(p));
    return a;
}
#define CP_ASYNC16CG(saddr, gptr)                                                \
    asm volatile("cp.async.cg.shared.global [%0], [%1], 16;"                     \
                 :: "r"(saddr), "l"(__cvta_generic_to_global(gptr)) : "memory")
#define CP_ASYNC16CGZ(saddr, gptr, sz)                                           \
    asm volatile("cp.async.cg.shared.global [%0], [%1], 16, %2;"                 \
                 :: "r"(saddr), "l"(__cvta_generic_to_global(gptr)), "r"(sz) : "memory")
#define CP_COMMIT() asm volatile("cp.async.commit_group;" ::: "memory")
#define CP_WAIT(N)  asm volatile("cp.async.wait_group %0;" :: "n"(N) : "memory")
#define LDSM4(r, addr)                                                           \
    asm volatile("ldmatrix.sync.aligned.m8n8.x4.shared.b16 {%0,%1,%2,%3}, [%4];" \
                 : "=r"((r)[0]), "=r"((r)[1]), "=r"((r)[2]), "=r"((r)[3])        \
                 : "r"(addr))
#define MMA16816(d, a, b0, b1)                                                   \
    asm volatile("mma.sync.aligned.m16n8k16.row.col.f32.f16.f16.f32 "            \
                 "{%0,%1,%2,%3}, {%4,%5,%6,%7}, {%8,%9}, {%0,%1,%2,%3};"         \
                 : "+f"((d)[0]), "+f"((d)[1]), "+f"((d)[2]), "+f"((d)[3])        \
                 : "r"((a)[0]), "r"((a)[1]), "r"((a)[2]), "r"((a)[3]),           \
                   "r"(b0), "r"(b1))
#define LDS128F(v, addr)                                                         \
    asm volatile("ld.shared.v4.f32 {%0,%1,%2,%3}, [%4];"                         \
                 : "=f"((v).x), "=f"((v).y), "=f"((v).z), "=f"((v).w) : "r"(addr))
#define STS16(addr, u0, u1, u2, u3)                                              \
    asm volatile("st.shared.v4.b32 [%0], {%1,%2,%3,%4};"                         \
                 :: "r"(addr), "r"(u0), "r"(u1), "r"(u2), "r"(u3) : "memory")

__device__ __forceinline__ uint32_t packh2(float a, float b) {
    __half2 h = __floats2half2_rn(a, b);
    return *reinterpret_cast<uint32_t*>(&h);
}

// =====================================================================
// Prep: cuts + normalized fp16 queries (inputs disambiguated on-device)
// =====================================================================
__global__ __launch_bounds__(256) void prep_kernel(
    const float* __restrict__ cand0, const float* __restrict__ cand1)
{
    __shared__ float sred[3 * 8];
    __shared__ float s_inv;
    bool c0_neg = false;
    #pragma unroll
    for (int i = 0; i < 64; ++i) c0_neg |= (cand0[i] < 0.f);
    const float* queries = c0_neg ? cand0 : cand1;
    const float* truths  = c0_neg ? cand1 : cand0;

    int q = blockIdx.x;
    int tid = threadIdx.x;
    const float* qp = queries + (size_t)q * DIM;
    const float* tp = truths + (size_t)q * DIM;

    float qq = 0.f, tt = 0.f, qt = 0.f;
    for (int i = tid; i < DIM; i += 256) {
        float a = qp[i], b = tp[i];
        qq = fmaf(a, a, qq); tt = fmaf(b, b, tt); qt = fmaf(a, b, qt);
    }
    #pragma unroll
    for (int o = 16; o; o >>= 1) {
        qq += __shfl_down_sync(0xffffffffu, qq, o);
        tt += __shfl_down_sync(0xffffffffu, tt, o);
        qt += __shfl_down_sync(0xffffffffu, qt, o);
    }
    if ((tid & 31) == 0) {
        int w = tid >> 5;
        sred[w] = qq; sred[8 + w] = tt; sred[16 + w] = qt;
    }
    __syncthreads();
    if (tid == 0) {
        float QQ = 0.f, TT = 0.f, QT = 0.f;
        #pragma unroll
        for (int w = 0; w < 8; ++w) { QQ += sred[w]; TT += sred[8 + w]; QT += sred[16 + w]; }
        float nq = fmaxf(sqrtf(QQ), 1e-12f);
        float nt = fmaxf(sqrtf(TT), 1e-12f);
        float th = QT / (nq * nt);
        g_cut[q] = th - (1e-8f + 1e-5f * fabsf(th));
        s_inv = 1.0f / nq;
    }
    __syncthreads();
    float inv = s_inv;
    for (int i = tid; i < DIM; i += 256)
        g_qh[(size_t)q * DIM + i] = __float2half_rn(qp[i] * inv);
}

// =====================================================================
// Main: 128x256 fp16 mma.sync GEMM, fused convert+norms,
//       single-barrier pipeline, MMA-first phase order, .cg staging
// =====================================================================
static constexpr uint32_t A32SZ = MT * PS;   // 18432
static constexpr uint32_t A16SZ = MT * RS;   // 10240
static constexpr uint32_t BSZ   = NT * RS;   // 20480

struct __align__(16) GSmem {
    float cut[NT];
    int   cnt[NT];
    float srn2[MT];
    int   last;
    int   pad[3];
    __align__(16) char a32[STAGES][A32SZ];
    __align__(16) char a16[2][A16SZ];
    __align__(16) char b[STAGES][BSZ];
};
static constexpr uint32_t SMEM_SZ = sizeof(GSmem);   // ~179KB

__global__ __launch_bounds__(NTHREADS, 1) void gemm_count_kernel(
    const float* __restrict__ data, int n_rows, float* __restrict__ out)
{
    extern __shared__ __align__(16) char smraw[];
    GSmem& s = *reinterpret_cast<GSmem*>(smraw);
    const uint32_t a32_base = smem_u32(s.a32);
    const uint32_t a16_base = smem_u32(s.a16);
    const uint32_t b_base   = smem_u32(s.b);
    const int tid  = threadIdx.x;
    const int lane = tid & 31;
    const int wid  = tid >> 5;          // 0..15
    const int wm   = wid & 1;           // M half (64 rows)
    const int wn   = wid >> 1;          // N eighth (32 cols)
    const int nb   = blockIdx.x;        // 0..1
    const int qb   = nb * NT;
    const int m_base = blockIdx.y * MT;

    for (int i = tid; i < NT; i += NTHREADS) {
        s.cut[i] = g_cut[qb + i];
        s.cnt[i] = 0;
    }
    if (tid < MT) s.srn2[tid] = 0.f;

    const __half* gB = g_qh + (size_t)qb * DIM;
    auto cp = [&](int it) {
        const int p = it % STAGES;
        const int k0 = it * KC;
        #pragma unroll
        for (int i = 0; i < 2; ++i) {                     // A fp32: 1024 16B segs
            int idx = tid + i * NTHREADS;
            int row = idx >> 3, c = idx & 7;
            uint32_t sz = (m_base + row) < n_rows ? 16u : 0u;
            CP_ASYNC16CGZ(a32_base + p * A32SZ + row * PS + c * 16,
                          data + (size_t)(m_base + row) * DIM + k0 + c * 4, sz);
        }
        #pragma unroll
        for (int i = 0; i < 2; ++i) {                     // B fp16: 1024 segs
            int idx = tid + i * NTHREADS;
            int row = idx >> 2, c = idx & 3;
            CP_ASYNC16CG(b_base + p * BSZ + row * RS + c * 16,
                         gB + (size_t)row * DIM + k0 + c * 8);
        }
    };

    float acc[4][4][4];
    #pragma unroll
    for (int i = 0; i < 4; ++i)
        #pragma unroll
        for (int j = 0; j < 4; ++j)
            #pragma unroll
            for (int k = 0; k < 4; ++k) acc[i][j][k] = 0.f;

    // convert mapping: row = tid&127, 8-float segment h = tid>>7
    const int crow = tid & 127;
    const int ch   = tid >> 7;
    const uint32_t cv_src0 = a32_base + (uint32_t)crow * PS + ch * 32;
    const uint32_t cv_dst0 = a16_base + (uint32_t)crow * RS + ch * 16;
    float norm2 = 0.f;

    // ldmatrix base offsets (audited mappings)
    const uint32_t a_off0 = (uint32_t)(wm * 64 + (lane & 15)) * RS + (lane >> 4) * 16;
    const uint32_t b_off0 = (uint32_t)(wn * 32 + ((lane >> 4) << 3) + (lane & 7)) * RS
                          + ((lane >> 3) & 1) * 16;

    cp(0); CP_COMMIT();
    cp(1); CP_COMMIT();
    CP_WAIT(1);                 // own cp(0) complete

    for (int it = 0; it <= NCH; ++it) {
        __syncthreads();        // publishes convert(it-1) a16 + cp(it) stages;
                                // retires mma(it-2)

        if (it >= 1) {
            // ---- MMA FIRST: chunk `it-1` from a16[(it-1)&1], b[(it-1)%4] ----
            const int mi = it - 1;
            const uint32_t a_fr = a16_base + (uint32_t)(mi & 1) * A16SZ + a_off0;
            const uint32_t b_fr = b_base + (uint32_t)(mi % STAGES) * BSZ + b_off0;
            #pragma unroll
            for (int ks = 0; ks < 2; ++ks) {
                uint32_t af[4][4];
                #pragma unroll
                for (int ma = 0; ma < 4; ++ma)
                    LDSM4(af[ma], a_fr + (uint32_t)ma * 16 * RS + ks * 32);
                uint32_t bf[2][4];
                #pragma unroll
                for (int pr = 0; pr < 2; ++pr)
                    LDSM4(bf[pr], b_fr + (uint32_t)pr * 16 * RS + ks * 32);
                #pragma unroll
                for (int np = 0; np < 4; ++np) {
                    uint32_t b0 = bf[np >> 1][(np & 1) * 2];
                    uint32_t b1 = bf[np >> 1][(np & 1) * 2 + 1];
                    #pragma unroll
                    for (int ma = 0; ma < 4; ++ma)
                        MMA16816(acc[ma][np], af[ma], b0, b1);
                }
            }
        }

        if (it < NCH) {
            // ---- convert chunk `it`: fp32 stage -> fp16 a16[it&1] + norm2 ----
            const uint32_t srcb = cv_src0 + (uint32_t)(it % STAGES) * A32SZ;
            float4 v0, v1;
            LDS128F(v0, srcb);
            LDS128F(v1, srcb + 16);
            norm2 = fmaf(v0.x, v0.x, norm2); norm2 = fmaf(v0.y, v0.y, norm2);
            norm2 = fmaf(v0.z, v0.z, norm2); norm2 = fmaf(v0.w, v0.w, norm2);
            norm2 = fmaf(v1.x, v1.x, norm2); norm2 = fmaf(v1.y, v1.y, norm2);
            norm2 = fmaf(v1.z, v1.z, norm2); norm2 = fmaf(v1.w, v1.w, norm2);
            STS16(cv_dst0 + (uint32_t)(it & 1) * A16SZ,
                  packh2(v0.x, v0.y), packh2(v0.z, v0.w),
                  packh2(v1.x, v1.y), packh2(v1.z, v1.w));
        }
        if (it + 2 < NCH) cp(it + 2);
        CP_COMMIT();
        CP_WAIT(1);             // own cp(it+1) complete (published next barrier)
    }

    // ---- finish row norms ----
    atomicAdd(&s.srn2[crow], norm2);
    __syncthreads();

    // ---- count epilogue ----
    float nr0v[4], nr1v[4];
    bool  ok0v[4], ok1v[4];
    #pragma unroll
    for (int ma = 0; ma < 4; ++ma) {
        int l0 = wm * 64 + ma * 16 + (lane >> 2);
        nr0v[ma] = sqrtf(s.srn2[l0]);
        nr1v[ma] = sqrtf(s.srn2[l0 + 8]);
        ok0v[ma] = (m_base + l0) < n_rows;
        ok1v[ma] = (m_base + l0 + 8) < n_rows;
    }
    #pragma unroll
    for (int na = 0; na < 4; ++na) {
        int cn = wn * 32 + na * 8 + 2 * (lane & 3);
        float cut0 = s.cut[cn], cut1 = s.cut[cn + 1];
        int c0 = 0, c1 = 0;
        #pragma unroll
        for (int ma = 0; ma < 4; ++ma) {
            c0 += (ok0v[ma] && acc[ma][na][0] >= nr0v[ma] * cut0);
            c0 += (ok1v[ma] && acc[ma][na][2] >= nr1v[ma] * cut0);
            c1 += (ok0v[ma] && acc[ma][na][1] >= nr0v[ma] * cut1);
            c1 += (ok1v[ma] && acc[ma][na][3] >= nr1v[ma] * cut1);
        }
        int pk = c0 | (c1 << 16);
        pk += __shfl_xor_sync(0xffffffffu, pk, 4);
        pk += __shfl_xor_sync(0xffffffffu, pk, 8);
        pk += __shfl_xor_sync(0xffffffffu, pk, 16);
        if (lane < 4) {
            atomicAdd(&s.cnt[cn], pk & 0xffff);
            atomicAdd(&s.cnt[cn + 1], pk >> 16);
        }
    }
    __syncthreads();

    // ---- cross-CTA last-block reduction (float output) ----
    if (tid < NT) atomicAdd(&g_part[qb + tid], s.cnt[tid]);
    __threadfence();
    __syncthreads();
    if (tid == 0) {
        unsigned t = atomicAdd(&g_done[nb], 1u);
        s.last = (t == gridDim.y - 1);
    }
    __syncthreads();
    if (s.last) {
        __threadfence();
        if (tid < NT) {
            int v = atomicExch(&g_part[qb + tid], 0);
            out[qb + tid] = (float)(v - 1);
        }
        if (tid == 0) atomicExch(&g_done[nb], 0u);
    }
}

// =====================================================================
extern "C" void kernel_launch(void* const* d_in, const int* in_sizes, int n_in,
                              void* d_out, int out_size)
{
    int i_data = 0;
    for (int i = 1; i < n_in && i < 3; ++i)
        if (in_sizes[i] > in_sizes[i_data]) i_data = i;
    int i_c0 = (i_data == 0) ? 1 : 0;
    int i_c1 = 3 - i_data - i_c0;

    const float* data  = (const float*)d_in[i_data];
    const float* cand0 = (const float*)d_in[i_c0];
    const float* cand1 = (const float*)d_in[i_c1];
    float* out = (float*)d_out;
    const int n_rows = in_sizes[i_data] / DIM;       // 50000

    prep_kernel<<<NQ, 256>>>(cand0, cand1);

    cudaFuncSetAttribute(gemm_count_kernel,
                         cudaFuncAttributeMaxDynamicSharedMemorySize, SMEM_SZ);
    dim3 grid(NQ / NT, (n_rows + MT - 1) / MT);      // (2, 391)
    gemm_count_kernel<<<grid, NTHREADS, SMEM_SZ>>>(data, n_rows, out);
}